// round 10
// baseline (speedup 1.0000x reference)
#include <cuda_runtime.h>
#include <cuda_bf16.h>
#include <cstdint>
#include <math.h>

// Problem constants
#define S_LEN   2048
#define D_MODEL 768
#define H_NUM   12
#define HD      64
#define B_SZ    2
#define M_ROWS  (B_SZ * S_LEN)   // 4096
#define W_ELEMS (D_MODEL * D_MODEL)

// Q pre-scale: 1/sqrt(64) * log2(e)  (softmax done in exp2 domain)
#define ALPHA_Q (0.125f * 1.44269504088896f)

// Scratch (allocation-free rule: __device__ globals). All bf16 hi/lo pairs.
__device__ __nv_bfloat16 g_xh[M_ROWS * D_MODEL];
__device__ __nv_bfloat16 g_xl[M_ROWS * D_MODEL];
__device__ __nv_bfloat16 g_wh[4 * W_ELEMS];
__device__ __nv_bfloat16 g_wl[4 * W_ELEMS];
__device__ __nv_bfloat16 g_qh[M_ROWS * D_MODEL];
__device__ __nv_bfloat16 g_ql[M_ROWS * D_MODEL];
__device__ __nv_bfloat16 g_kh[M_ROWS * D_MODEL];
__device__ __nv_bfloat16 g_kl[M_ROWS * D_MODEL];
__device__ __nv_bfloat16 g_vh[M_ROWS * D_MODEL];
__device__ __nv_bfloat16 g_vl[M_ROWS * D_MODEL];
__device__ __nv_bfloat16 g_ch[M_ROWS * D_MODEL];
__device__ __nv_bfloat16 g_cl[M_ROWS * D_MODEL];

// ===========================================================================
// Warp-MMA + async-copy helpers
// ===========================================================================
__device__ __forceinline__ uint32_t smem_to_u32(const void* p) {
    uint32_t a;
    asm("{ .reg .u64 t; cvta.to.shared.u64 t, %1; cvt.u32.u64 %0, t; }"
        : "=r"(a) : "l"(p));
    return a;
}
__device__ __forceinline__ void ldsm_x4(uint32_t* r, uint32_t addr) {
    asm volatile(
        "ldmatrix.sync.aligned.m8n8.x4.shared.b16 {%0,%1,%2,%3}, [%4];"
        : "=r"(r[0]), "=r"(r[1]), "=r"(r[2]), "=r"(r[3]) : "r"(addr));
}
__device__ __forceinline__ void ldsm_x4_t(uint32_t* r, uint32_t addr) {
    asm volatile(
        "ldmatrix.sync.aligned.m8n8.x4.trans.shared.b16 {%0,%1,%2,%3}, [%4];"
        : "=r"(r[0]), "=r"(r[1]), "=r"(r[2]), "=r"(r[3]) : "r"(addr));
}
__device__ __forceinline__ void mma_bf16(float* c, const uint32_t* a,
                                         uint32_t b0, uint32_t b1) {
    asm volatile(
        "mma.sync.aligned.m16n8k16.row.col.f32.bf16.bf16.f32 "
        "{%0,%1,%2,%3}, {%4,%5,%6,%7}, {%8,%9}, {%0,%1,%2,%3};"
        : "+f"(c[0]), "+f"(c[1]), "+f"(c[2]), "+f"(c[3])
        : "r"(a[0]), "r"(a[1]), "r"(a[2]), "r"(a[3]), "r"(b0), "r"(b1));
}
__device__ __forceinline__ uint32_t cvt_bf16x2(float lo, float hi) {
    uint32_t r;
    asm("cvt.rn.bf16x2.f32 %0, %1, %2;" : "=r"(r) : "f"(hi), "f"(lo));
    return r;
}
__device__ __forceinline__ float bf16_rt(float x) {
    return __bfloat162float(__float2bfloat16(x));
}
__device__ __forceinline__ void cp_async16(uint32_t dst, const void* src) {
    asm volatile("cp.async.cg.shared.global [%0], [%1], 16;"
                 :: "r"(dst), "l"(src) : "memory");
}
#define CP_COMMIT() asm volatile("cp.async.commit_group;" ::: "memory")
#define CP_WAIT1()  asm volatile("cp.async.wait_group 1;" ::: "memory")
#define CP_WAIT0()  asm volatile("cp.async.wait_group 0;" ::: "memory")

// ===========================================================================
// Fused split: fp32 -> (bf16 hi, bf16 lo) for x + 4 weights in ONE launch.
// ===========================================================================
__global__ __launch_bounds__(256) void split_all_kernel(
    const float* __restrict__ x,
    const float* __restrict__ Wq, const float* __restrict__ Wk,
    const float* __restrict__ Wv, const float* __restrict__ Wo,
    __nv_bfloat16* __restrict__ xh, __nv_bfloat16* __restrict__ xl,
    __nv_bfloat16* __restrict__ wh, __nv_bfloat16* __restrict__ wl)
{
    const int t = blockIdx.y;
    const float* src;
    __nv_bfloat16 *hi, *lo;
    int n4;
    if (t == 0) { src = x;  hi = xh; lo = xl; n4 = M_ROWS * D_MODEL / 4; }
    else {
        const float* ws[4] = {Wq, Wk, Wv, Wo};
        src = ws[t - 1];
        hi = wh + (size_t)(t - 1) * W_ELEMS;
        lo = wl + (size_t)(t - 1) * W_ELEMS;
        n4 = W_ELEMS / 4;
    }
    int i = blockIdx.x * blockDim.x + threadIdx.x;
    if (i >= n4) return;
    float4 v = reinterpret_cast<const float4*>(src)[i];
    __nv_bfloat16 hx = __float2bfloat16(v.x);
    __nv_bfloat16 hy = __float2bfloat16(v.y);
    __nv_bfloat16 hz = __float2bfloat16(v.z);
    __nv_bfloat16 hw = __float2bfloat16(v.w);
    __nv_bfloat162* hp = reinterpret_cast<__nv_bfloat162*>(hi) + 2 * i;
    hp[0] = __nv_bfloat162(hx, hy);
    hp[1] = __nv_bfloat162(hz, hw);
    __nv_bfloat162* lp = reinterpret_cast<__nv_bfloat162*>(lo) + 2 * i;
    lp[0] = __nv_bfloat162(__float2bfloat16(v.x - __bfloat162float(hx)),
                           __float2bfloat16(v.y - __bfloat162float(hy)));
    lp[1] = __nv_bfloat162(__float2bfloat16(v.z - __bfloat162float(hz)),
                           __float2bfloat16(v.w - __bfloat162float(hw)));
}

// ===========================================================================
// QKV GEMM: CTA tile 128x128, BK=32, 8 warps 4(M)x2(N), warp 32x64.
// Three-pass MMA order (hh, lh, hl). 2-stage cp.async.
// ===========================================================================
#define BM2 128
#define BN2 128
#define BK2 32
#define LDA2 40
#define LDB2 136
#define G2_AH 0
#define G2_AL 10240
#define G2_BH 20480
#define G2_BL 29184
#define G2_STAGE 37888
#define SM_G2_TOTAL (2 * G2_STAGE)   // 75776
#define NCH2 (D_MODEL / BK2)         // 24

__device__ __forceinline__ void gemm2_issue_loads(
    uint32_t sb, uint32_t stg, int tid, int m0, int n0, int k0,
    const __nv_bfloat16* Ah, const __nv_bfloat16* Al,
    const __nv_bfloat16* Bh, const __nv_bfloat16* Bl)
{
#pragma unroll
    for (int it = 0; it < 2; it++) {
        const int idx = tid + it * 256;
        {
            const int r = idx >> 2, c8 = (idx & 3) * 8;
            const size_t g = (size_t)(m0 + r) * D_MODEL + k0 + c8;
            const uint32_t so = (uint32_t)(r * LDA2 + c8) * 2;
            cp_async16(sb + stg + G2_AH + so, &Ah[g]);
            cp_async16(sb + stg + G2_AL + so, &Al[g]);
        }
        {
            const int r = idx >> 4, n8 = (idx & 15) * 8;
            const size_t g = (size_t)(k0 + r) * D_MODEL + n0 + n8;
            const uint32_t so = (uint32_t)(r * LDB2 + n8) * 2;
            cp_async16(sb + stg + G2_BH + so, &Bh[g]);
            cp_async16(sb + stg + G2_BL + so, &Bl[g]);
        }
    }
}

__device__ __forceinline__ void gemm2_compute_chunk(
    uint32_t sb, uint32_t stg, int lane, int wm, int wn, float c[2][8][4])
{
    const int a_row = lane & 15;
    const int a_kc  = (lane >> 4) * 8;
    const int b_k   = lane & 15;
    const int b_n   = (lane >> 4) * 8;
#pragma unroll
    for (int ks = 0; ks < BK2 / 16; ks++) {
        uint32_t ah0[4], ah1[4], al0[4], al1[4];
        {
            const uint32_t offH = stg + G2_AH +
                ((wm * 32 + a_row) * LDA2 + ks * 16 + a_kc) * 2;
            ldsm_x4(ah0, sb + offH);
            ldsm_x4(ah1, sb + offH + 16 * LDA2 * 2);
            const uint32_t offL = stg + G2_AL +
                ((wm * 32 + a_row) * LDA2 + ks * 16 + a_kc) * 2;
            ldsm_x4(al0, sb + offL);
            ldsm_x4(al1, sb + offL + 16 * LDA2 * 2);
        }
        uint32_t bh[4][4];
#pragma unroll
        for (int nb = 0; nb < 4; nb++) {
            const uint32_t offB = stg + G2_BH +
                ((ks * 16 + b_k) * LDB2 + wn * 64 + nb * 16 + b_n) * 2;
            ldsm_x4_t(bh[nb], sb + offB);
        }
#pragma unroll
        for (int nb = 0; nb < 4; nb++) {
            mma_bf16(c[0][2 * nb],     ah0, bh[nb][0], bh[nb][1]);
            mma_bf16(c[1][2 * nb],     ah1, bh[nb][0], bh[nb][1]);
            mma_bf16(c[0][2 * nb + 1], ah0, bh[nb][2], bh[nb][3]);
            mma_bf16(c[1][2 * nb + 1], ah1, bh[nb][2], bh[nb][3]);
        }
#pragma unroll
        for (int nb = 0; nb < 4; nb++) {
            mma_bf16(c[0][2 * nb],     al0, bh[nb][0], bh[nb][1]);
            mma_bf16(c[1][2 * nb],     al1, bh[nb][0], bh[nb][1]);
            mma_bf16(c[0][2 * nb + 1], al0, bh[nb][2], bh[nb][3]);
            mma_bf16(c[1][2 * nb + 1], al1, bh[nb][2], bh[nb][3]);
        }
#pragma unroll
        for (int nb = 0; nb < 4; nb++) {
            uint32_t bl[4];
            const uint32_t offB = stg + G2_BL +
                ((ks * 16 + b_k) * LDB2 + wn * 64 + nb * 16 + b_n) * 2;
            ldsm_x4_t(bl, sb + offB);
            mma_bf16(c[0][2 * nb],     ah0, bl[0], bl[1]);
            mma_bf16(c[1][2 * nb],     ah1, bl[0], bl[1]);
            mma_bf16(c[0][2 * nb + 1], ah0, bl[2], bl[3]);
            mma_bf16(c[1][2 * nb + 1], ah1, bl[2], bl[3]);
        }
    }
}

__global__ __launch_bounds__(256, 2) void gemm_qkv_kernel(
    const __nv_bfloat16* __restrict__ Ah, const __nv_bfloat16* __restrict__ Al,
    const __nv_bfloat16* __restrict__ whb, const __nv_bfloat16* __restrict__ wlb,
    const float* __restrict__ bq, const float* __restrict__ bk,
    const float* __restrict__ bv,
    __nv_bfloat16* __restrict__ qh, __nv_bfloat16* __restrict__ ql,
    __nv_bfloat16* __restrict__ kh, __nv_bfloat16* __restrict__ kl,
    __nv_bfloat16* __restrict__ vh, __nv_bfloat16* __restrict__ vl)
{
    extern __shared__ char smg[];
    const uint32_t sb = smem_to_u32(smg);
    const int tid  = threadIdx.x;
    const int lane = tid & 31;
    const int w    = tid >> 5;
    const int wm   = w & 3;
    const int wn   = w >> 2;
    const int m0   = blockIdx.x * BM2;
    const int n0   = blockIdx.y * BN2;
    const int z    = blockIdx.z;

    const __nv_bfloat16* Bh = whb + (size_t)z * W_ELEMS;
    const __nv_bfloat16* Bl = wlb + (size_t)z * W_ELEMS;
    const float* bias = (z == 0) ? bq : (z == 1) ? bk : bv;
    const float alpha = (z == 0) ? ALPHA_Q : 1.0f;
    __nv_bfloat16* Ch = (z == 0) ? qh : (z == 1) ? kh : vh;
    __nv_bfloat16* Cl = (z == 0) ? ql : (z == 1) ? kl : vl;

    float c[2][8][4];
#pragma unroll
    for (int mt = 0; mt < 2; mt++)
#pragma unroll
        for (int nt = 0; nt < 8; nt++)
#pragma unroll
            for (int j = 0; j < 4; j++) c[mt][nt][j] = 0.0f;

    gemm2_issue_loads(sb, 0, tid, m0, n0, 0, Ah, Al, Bh, Bl);
    CP_COMMIT();

    for (int ch = 0; ch < NCH2; ch++) {
        const uint32_t cur = (ch & 1) * G2_STAGE;
        if (ch + 1 < NCH2) {
            gemm2_issue_loads(sb, cur ^ G2_STAGE, tid, m0, n0,
                              (ch + 1) * BK2, Ah, Al, Bh, Bl);
            CP_COMMIT();
            CP_WAIT1();
        } else {
            CP_WAIT0();
        }
        __syncthreads();
        gemm2_compute_chunk(sb, cur, lane, wm, wn, c);
        __syncthreads();
    }

#pragma unroll
    for (int mt = 0; mt < 2; mt++) {
        const int mrow = m0 + wm * 32 + mt * 16 + (lane >> 2);
#pragma unroll
        for (int nt = 0; nt < 8; nt++) {
            const int ncol = n0 + wn * 64 + nt * 8 + (lane & 3) * 2;
            const float b0 = bias[ncol], b1 = bias[ncol + 1];
            const float v00 = alpha * (c[mt][nt][0] + b0);
            const float v01 = alpha * (c[mt][nt][1] + b1);
            const float v10 = alpha * (c[mt][nt][2] + b0);
            const float v11 = alpha * (c[mt][nt][3] + b1);
            const size_t g0 = (size_t)mrow * D_MODEL + ncol;
            const size_t g1 = (size_t)(mrow + 8) * D_MODEL + ncol;
            *reinterpret_cast<uint32_t*>(&Ch[g0]) = cvt_bf16x2(v00, v01);
            *reinterpret_cast<uint32_t*>(&Ch[g1]) = cvt_bf16x2(v10, v11);
            *reinterpret_cast<uint32_t*>(&Cl[g0]) =
                cvt_bf16x2(v00 - bf16_rt(v00), v01 - bf16_rt(v01));
            *reinterpret_cast<uint32_t*>(&Cl[g1]) =
                cvt_bf16x2(v10 - bf16_rt(v10), v11 - bf16_rt(v11));
        }
    }
}

// ===========================================================================
// O-projection GEMM: BM=64 x BN=64, 128 threads (4 warps 2x2, warp 32x32).
// 768 tiles; smem padded to cap occupancy at 3 CTA/SM (768/444 = 1.73 waves).
// ===========================================================================
#define LDBO 72
#define GO_AH 0
#define GO_AL 5120
#define GO_BH 10240
#define GO_BL 14848
#define GO_STAGE 19456
#define SM_GO_TOTAL 58368   // 2*19456 = 38912, padded to force <=3 CTA/SM

__device__ __forceinline__ void gemmo_issue_loads(
    uint32_t sb, uint32_t stg, int tid, int m0, int n0, int k0,
    const __nv_bfloat16* Ah, const __nv_bfloat16* Al,
    const __nv_bfloat16* Bh, const __nv_bfloat16* Bl)
{
#pragma unroll
    for (int it = 0; it < 2; it++) {
        const int idx = tid + it * 128;
        // A: 64 rows x 32 k -> 256 uint4
        {
            const int r = idx >> 2, c8 = (idx & 3) * 8;
            const size_t g = (size_t)(m0 + r) * D_MODEL + k0 + c8;
            const uint32_t so = (uint32_t)(r * LDA2 + c8) * 2;
            cp_async16(sb + stg + GO_AH + so, &Ah[g]);
            cp_async16(sb + stg + GO_AL + so, &Al[g]);
        }
        // B: 32 k x 64 n -> 256 uint4
        {
            const int r = idx >> 3, n8 = (idx & 7) * 8;
            const size_t g = (size_t)(k0 + r) * D_MODEL + n0 + n8;
            const uint32_t so = (uint32_t)(r * LDBO + n8) * 2;
            cp_async16(sb + stg + GO_BH + so, &Bh[g]);
            cp_async16(sb + stg + GO_BL + so, &Bl[g]);
        }
    }
}

__global__ __launch_bounds__(128) void gemm_o_kernel(
    const __nv_bfloat16* __restrict__ Ah, const __nv_bfloat16* __restrict__ Al,
    const __nv_bfloat16* __restrict__ Bh, const __nv_bfloat16* __restrict__ Bl,
    const float* __restrict__ bias, float* __restrict__ Cf)
{
    extern __shared__ char smg[];
    const uint32_t sb = smem_to_u32(smg);
    const int tid  = threadIdx.x;
    const int lane = tid & 31;
    const int w    = tid >> 5;
    const int wm   = w & 1;          // 2 M-warps
    const int wn   = w >> 1;         // 2 N-warps
    const int m0   = blockIdx.x * 64;
    const int n0   = blockIdx.y * 64;

    const int a_row = lane & 15;
    const int a_kc  = (lane >> 4) * 8;
    const int b_k   = lane & 15;
    const int b_n   = (lane >> 4) * 8;

    float c[2][4][4];
#pragma unroll
    for (int mt = 0; mt < 2; mt++)
#pragma unroll
        for (int nt = 0; nt < 4; nt++)
#pragma unroll
            for (int j = 0; j < 4; j++) c[mt][nt][j] = 0.0f;

    gemmo_issue_loads(sb, 0, tid, m0, n0, 0, Ah, Al, Bh, Bl);
    CP_COMMIT();

    for (int ch = 0; ch < NCH2; ch++) {
        const uint32_t cur = (ch & 1) * GO_STAGE;
        if (ch + 1 < NCH2) {
            gemmo_issue_loads(sb, cur ^ GO_STAGE, tid, m0, n0,
                              (ch + 1) * BK2, Ah, Al, Bh, Bl);
            CP_COMMIT();
            CP_WAIT1();
        } else {
            CP_WAIT0();
        }
        __syncthreads();

#pragma unroll
        for (int ks = 0; ks < BK2 / 16; ks++) {
            uint32_t ah0[4], ah1[4], al0[4], al1[4];
            {
                const uint32_t offH = cur + GO_AH +
                    ((wm * 32 + a_row) * LDA2 + ks * 16 + a_kc) * 2;
                ldsm_x4(ah0, sb + offH);
                ldsm_x4(ah1, sb + offH + 16 * LDA2 * 2);
                const uint32_t offL = cur + GO_AL +
                    ((wm * 32 + a_row) * LDA2 + ks * 16 + a_kc) * 2;
                ldsm_x4(al0, sb + offL);
                ldsm_x4(al1, sb + offL + 16 * LDA2 * 2);
            }
            uint32_t bh[2][4];
#pragma unroll
            for (int nb = 0; nb < 2; nb++) {
                const uint32_t offB = cur + GO_BH +
                    ((ks * 16 + b_k) * LDBO + wn * 32 + nb * 16 + b_n) * 2;
                ldsm_x4_t(bh[nb], sb + offB);
            }
#pragma unroll
            for (int nb = 0; nb < 2; nb++) {
                mma_bf16(c[0][2 * nb],     ah0, bh[nb][0], bh[nb][1]);
                mma_bf16(c[1][2 * nb],     ah1, bh[nb][0], bh[nb][1]);
                mma_bf16(c[0][2 * nb + 1], ah0, bh[nb][2], bh[nb][3]);
                mma_bf16(c[1][2 * nb + 1], ah1, bh[nb][2], bh[nb][3]);
            }
#pragma unroll
            for (int nb = 0; nb < 2; nb++) {
                mma_bf16(c[0][2 * nb],     al0, bh[nb][0], bh[nb][1]);
                mma_bf16(c[1][2 * nb],     al1, bh[nb][0], bh[nb][1]);
                mma_bf16(c[0][2 * nb + 1], al0, bh[nb][2], bh[nb][3]);
                mma_bf16(c[1][2 * nb + 1], al1, bh[nb][2], bh[nb][3]);
            }
#pragma unroll
            for (int nb = 0; nb < 2; nb++) {
                uint32_t bl[4];
                const uint32_t offB = cur + GO_BL +
                    ((ks * 16 + b_k) * LDBO + wn * 32 + nb * 16 + b_n) * 2;
                ldsm_x4_t(bl, sb + offB);
                mma_bf16(c[0][2 * nb],     ah0, bl[0], bl[1]);
                mma_bf16(c[1][2 * nb],     ah1, bl[0], bl[1]);
                mma_bf16(c[0][2 * nb + 1], ah0, bl[2], bl[3]);
                mma_bf16(c[1][2 * nb + 1], ah1, bl[2], bl[3]);
            }
        }
        __syncthreads();
    }

#pragma unroll
    for (int mt = 0; mt < 2; mt++) {
        const int mrow = m0 + wm * 32 + mt * 16 + (lane >> 2);
#pragma unroll
        for (int nt = 0; nt < 4; nt++) {
            const int ncol = n0 + wn * 32 + nt * 8 + (lane & 3) * 2;
            const float b0 = bias[ncol], b1 = bias[ncol + 1];
            float2 o0 = make_float2(c[mt][nt][0] + b0, c[mt][nt][1] + b1);
            float2 o1 = make_float2(c[mt][nt][2] + b0, c[mt][nt][3] + b1);
            *reinterpret_cast<float2*>(&Cf[(size_t)mrow * D_MODEL + ncol]) = o0;
            *reinterpret_cast<float2*>(&Cf[(size_t)(mrow + 8) * D_MODEL + ncol]) = o1;
        }
    }
}

// ===========================================================================
// HMMA flash attention: BQ=64, 128 threads (4 warps; warp = 16 query rows).
// 768 CTAs at 2/SM -> 86% wave fill. 2-stage cp.async; exp2-domain softmax.
// smem: Q (hi+lo) 18432 + 2 stages x 36864 = 92160 B.
// ===========================================================================
#define AT_LD 72
#define A_QH 0
#define A_QL 9216
#define A_QSZ 18432
#define A_KH 0
#define A_KL 9216
#define A_VH 18432
#define A_VL 27648
#define A_STAGE 36864
#define A_SM_TOTAL (A_QSZ + 2 * A_STAGE)   // 92160

__device__ __forceinline__ void attn_issue_loads(
    uint32_t sb, uint32_t stg, int tid, size_t rbase, int kt, int hcol,
    const __nv_bfloat16* Kh, const __nv_bfloat16* Kl,
    const __nv_bfloat16* Vh, const __nv_bfloat16* Vl)
{
    const int r  = tid >> 3;          // 0..15
    const int c8 = (tid & 7) * 8;
#pragma unroll
    for (int it = 0; it < 4; it++) {
        const int rr = r + it * 16;
        const size_t g = (rbase + kt + rr) * D_MODEL + hcol + c8;
        const uint32_t so = (uint32_t)(rr * AT_LD + c8) * 2;
        cp_async16(sb + stg + A_KH + so, &Kh[g]);
        cp_async16(sb + stg + A_KL + so, &Kl[g]);
        cp_async16(sb + stg + A_VH + so, &Vh[g]);
        cp_async16(sb + stg + A_VL + so, &Vl[g]);
    }
}

__global__ __launch_bounds__(128, 2) void attn_hmma_kernel(
    const __nv_bfloat16* __restrict__ Qh, const __nv_bfloat16* __restrict__ Ql,
    const __nv_bfloat16* __restrict__ Kh, const __nv_bfloat16* __restrict__ Kl,
    const __nv_bfloat16* __restrict__ Vh, const __nv_bfloat16* __restrict__ Vl,
    __nv_bfloat16* __restrict__ Ch, __nv_bfloat16* __restrict__ Cl)
{
    extern __shared__ char sma[];
    const uint32_t sb = smem_to_u32(sma);
    const int tid  = threadIdx.x;
    const int lane = tid & 31;
    const int w    = tid >> 5;        // 0..3
    const int q0   = blockIdx.x * 64;
    const int h    = blockIdx.y;
    const int b    = blockIdx.z;
    const int hcol = h * HD;
    const size_t rbase = (size_t)b * S_LEN;

    const int l_row = lane & 15;
    const int l_c8  = (lane >> 4) * 8;

    attn_issue_loads(sb, A_QSZ, tid, rbase, 0, hcol, Kh, Kl, Vh, Vl);
    CP_COMMIT();

    // load Q tile 64 x 64 (hi/lo)
    {
        const int r = tid >> 3;       // 0..15
        const int c8 = (tid & 7) * 8;
#pragma unroll
        for (int it = 0; it < 4; it++) {
            const int rr = r + it * 16;
            const size_t g = (rbase + q0 + rr) * D_MODEL + hcol + c8;
            *reinterpret_cast<uint4*>(sma + A_QH + (rr * AT_LD + c8) * 2) =
                *reinterpret_cast<const uint4*>(&Qh[g]);
            *reinterpret_cast<uint4*>(sma + A_QL + (rr * AT_LD + c8) * 2) =
                *reinterpret_cast<const uint4*>(&Ql[g]);
        }
    }

    float ctx[8][4];
#pragma unroll
    for (int nt = 0; nt < 8; nt++)
#pragma unroll
        for (int j = 0; j < 4; j++) ctx[nt][j] = 0.0f;
    float m0r = -INFINITY, m1r = -INFINITY, l0r = 0.0f, l1r = 0.0f;

    const int NT = S_LEN / 64;
    for (int ti = 0; ti < NT; ti++) {
        const uint32_t cur = A_QSZ + (ti & 1) * A_STAGE;
        if (ti + 1 < NT) {
            attn_issue_loads(sb, A_QSZ + ((ti + 1) & 1) * A_STAGE,
                             tid, rbase, (ti + 1) * 64, hcol, Kh, Kl, Vh, Vl);
            CP_COMMIT();
            CP_WAIT1();
        } else {
            CP_WAIT0();
        }
        __syncthreads();

        // ---- S = Q K^T, 3-term split
        float S[8][4];
#pragma unroll
        for (int nt = 0; nt < 8; nt++)
#pragma unroll
            for (int j = 0; j < 4; j++) S[nt][j] = 0.0f;

#pragma unroll
        for (int ks = 0; ks < 4; ks++) {
            uint32_t qh[4], ql[4];
            const uint32_t qoff = ((w * 16 + l_row) * AT_LD + ks * 16 + l_c8) * 2;
            ldsm_x4(qh, sb + A_QH + qoff);
            ldsm_x4(ql, sb + A_QL + qoff);
#pragma unroll
            for (int g = 0; g < 4; g++) {
                uint32_t kh[4], kl[4];
                const uint32_t koff = cur + A_KH +
                    ((g * 16 + l_row) * AT_LD + ks * 16 + l_c8) * 2;
                ldsm_x4(kh, sb + koff);
                ldsm_x4(kl, sb + koff + (A_KL - A_KH));
                mma_bf16(S[2 * g],     qh, kh[0], kh[2]);
                mma_bf16(S[2 * g + 1], qh, kh[1], kh[3]);
                mma_bf16(S[2 * g],     ql, kh[0], kh[2]);
                mma_bf16(S[2 * g + 1], ql, kh[1], kh[3]);
                mma_bf16(S[2 * g],     qh, kl[0], kl[2]);
                mma_bf16(S[2 * g + 1], qh, kl[1], kl[3]);
            }
        }

        // ---- online softmax (exp2 domain)
        float mx0 = -INFINITY, mx1 = -INFINITY;
#pragma unroll
        for (int nt = 0; nt < 8; nt++) {
            mx0 = fmaxf(mx0, fmaxf(S[nt][0], S[nt][1]));
            mx1 = fmaxf(mx1, fmaxf(S[nt][2], S[nt][3]));
        }
        mx0 = fmaxf(mx0, __shfl_xor_sync(0xffffffffu, mx0, 1));
        mx0 = fmaxf(mx0, __shfl_xor_sync(0xffffffffu, mx0, 2));
        mx1 = fmaxf(mx1, __shfl_xor_sync(0xffffffffu, mx1, 1));
        mx1 = fmaxf(mx1, __shfl_xor_sync(0xffffffffu, mx1, 2));
        const float mn0 = fmaxf(m0r, mx0);
        const float mn1 = fmaxf(m1r, mx1);
        const float cr0 = exp2f(m0r - mn0);
        const float cr1 = exp2f(m1r - mn1);
        float s0 = 0.0f, s1 = 0.0f;
#pragma unroll
        for (int nt = 0; nt < 8; nt++) {
            S[nt][0] = exp2f(S[nt][0] - mn0);
            S[nt][1] = exp2f(S[nt][1] - mn0);
            S[nt][2] = exp2f(S[nt][2] - mn1);
            S[nt][3] = exp2f(S[nt][3] - mn1);
            s0 += S[nt][0] + S[nt][1];
            s1 += S[nt][2] + S[nt][3];
            ctx[nt][0] *= cr0; ctx[nt][1] *= cr0;
            ctx[nt][2] *= cr1; ctx[nt][3] *= cr1;
        }
        s0 += __shfl_xor_sync(0xffffffffu, s0, 1);
        s0 += __shfl_xor_sync(0xffffffffu, s0, 2);
        s1 += __shfl_xor_sync(0xffffffffu, s1, 1);
        s1 += __shfl_xor_sync(0xffffffffu, s1, 2);
        l0r = l0r * cr0 + s0;
        l1r = l1r * cr1 + s1;
        m0r = mn0;
        m1r = mn1;

        // ---- pack P into a-frags (hi + lo)
        uint32_t ph[4][4], pl[4][4];
#pragma unroll
        for (int j = 0; j < 4; j++) {
            const float p0 = S[2 * j][0],     p1 = S[2 * j][1];
            const float p2 = S[2 * j][2],     p3 = S[2 * j][3];
            const float p4 = S[2 * j + 1][0], p5 = S[2 * j + 1][1];
            const float p6 = S[2 * j + 1][2], p7 = S[2 * j + 1][3];
            ph[j][0] = cvt_bf16x2(p0, p1);
            ph[j][1] = cvt_bf16x2(p2, p3);
            ph[j][2] = cvt_bf16x2(p4, p5);
            ph[j][3] = cvt_bf16x2(p6, p7);
            pl[j][0] = cvt_bf16x2(p0 - bf16_rt(p0), p1 - bf16_rt(p1));
            pl[j][1] = cvt_bf16x2(p2 - bf16_rt(p2), p3 - bf16_rt(p3));
            pl[j][2] = cvt_bf16x2(p4 - bf16_rt(p4), p5 - bf16_rt(p5));
            pl[j][3] = cvt_bf16x2(p6 - bf16_rt(p6), p7 - bf16_rt(p7));
        }

        // ---- ctx += P V
#pragma unroll
        for (int kc = 0; kc < 4; kc++) {
#pragma unroll
            for (int dg = 0; dg < 4; dg++) {
                uint32_t vh[4], vl[4];
                const uint32_t voff = cur + A_VH +
                    ((kc * 16 + l_row) * AT_LD + dg * 16 + l_c8) * 2;
                ldsm_x4_t(vh, sb + voff);
                ldsm_x4_t(vl, sb + voff + (A_VL - A_VH));
                mma_bf16(ctx[2 * dg],     ph[kc], vh[0], vh[1]);
                mma_bf16(ctx[2 * dg + 1], ph[kc], vh[2], vh[3]);
                mma_bf16(ctx[2 * dg],     pl[kc], vh[0], vh[1]);
                mma_bf16(ctx[2 * dg + 1], pl[kc], vh[2], vh[3]);
                mma_bf16(ctx[2 * dg],     ph[kc], vl[0], vl[1]);
                mma_bf16(ctx[2 * dg + 1], ph[kc], vl[2], vl[3]);
            }
        }
        __syncthreads();
    }

    // ---- epilogue
    const float inv0 = 1.0f / l0r;
    const float inv1 = 1.0f / l1r;
    const int row0 = q0 + w * 16 + (lane >> 2);
#pragma unroll
    for (int nt = 0; nt < 8; nt++) {
        const int col = hcol + nt * 8 + (lane & 3) * 2;
        const float v00 = ctx[nt][0] * inv0, v01 = ctx[nt][1] * inv0;
        const float v10 = ctx[nt][2] * inv1, v11 = ctx[nt][3] * inv1;
        const size_t g0 = (rbase + row0) * D_MODEL + col;
        const size_t g1 = (rbase + row0 + 8) * D_MODEL + col;
        *reinterpret_cast<uint32_t*>(&Ch[g0]) = cvt_bf16x2(v00, v01);
        *reinterpret_cast<uint32_t*>(&Ch[g1]) = cvt_bf16x2(v10, v11);
        *reinterpret_cast<uint32_t*>(&Cl[g0]) =
            cvt_bf16x2(v00 - bf16_rt(v00), v01 - bf16_rt(v01));
        *reinterpret_cast<uint32_t*>(&Cl[g1]) =
            cvt_bf16x2(v10 - bf16_rt(v10), v11 - bf16_rt(v11));
    }
}

// ---------------------------------------------------------------------------
// Launch
// ---------------------------------------------------------------------------
extern "C" void kernel_launch(void* const* d_in, const int* in_sizes, int n_in,
                              void* d_out, int out_size)
{
    const float* x  = (const float*)d_in[0];
    const float* Wq = (const float*)d_in[1];
    const float* bq = (const float*)d_in[2];
    const float* Wk = (const float*)d_in[3];
    const float* bk = (const float*)d_in[4];
    const float* Wv = (const float*)d_in[5];
    const float* bv = (const float*)d_in[6];
    const float* Wo = (const float*)d_in[7];
    const float* bo = (const float*)d_in[8];
    float* out = (float*)d_out;

    __nv_bfloat16 *xh, *xl, *wh, *wl, *qh, *ql, *kh, *kl, *vh, *vl, *ch, *cl;
    cudaGetSymbolAddress((void**)&xh, g_xh);
    cudaGetSymbolAddress((void**)&xl, g_xl);
    cudaGetSymbolAddress((void**)&wh, g_wh);
    cudaGetSymbolAddress((void**)&wl, g_wl);
    cudaGetSymbolAddress((void**)&qh, g_qh);
    cudaGetSymbolAddress((void**)&ql, g_ql);
    cudaGetSymbolAddress((void**)&kh, g_kh);
    cudaGetSymbolAddress((void**)&kl, g_kl);
    cudaGetSymbolAddress((void**)&vh, g_vh);
    cudaGetSymbolAddress((void**)&vl, g_vl);
    cudaGetSymbolAddress((void**)&ch, g_ch);
    cudaGetSymbolAddress((void**)&cl, g_cl);

    cudaFuncSetAttribute(gemm_qkv_kernel,
                         cudaFuncAttributeMaxDynamicSharedMemorySize,
                         SM_G2_TOTAL);
    cudaFuncSetAttribute(gemm_o_kernel,
                         cudaFuncAttributeMaxDynamicSharedMemorySize,
                         SM_GO_TOTAL);
    cudaFuncSetAttribute(attn_hmma_kernel,
                         cudaFuncAttributeMaxDynamicSharedMemorySize,
                         A_SM_TOTAL);

    dim3 split_grid((M_ROWS * D_MODEL / 4 + 255) / 256, 5);
    split_all_kernel<<<split_grid, 256>>>(x, Wq, Wk, Wv, Wo, xh, xl, wh, wl);

    dim3 qkv_grid(M_ROWS / BM2, D_MODEL / BN2, 3);   // 32 x 6 x 3
    gemm_qkv_kernel<<<qkv_grid, 256, SM_G2_TOTAL>>>(
        xh, xl, wh, wl, bq, bk, bv, qh, ql, kh, kl, vh, vl);

    dim3 attn_grid(S_LEN / 64, H_NUM, B_SZ);         // 32 x 12 x 2 = 768
    attn_hmma_kernel<<<attn_grid, 128, A_SM_TOTAL>>>(
        qh, ql, kh, kl, vh, vl, ch, cl);

    dim3 o_grid(M_ROWS / 64, D_MODEL / 64);          // 64 x 12 = 768
    gemm_o_kernel<<<o_grid, 128, SM_GO_TOTAL>>>(
        ch, cl, wh + 3 * W_ELEMS, wl + 3 * W_ELEMS, bo, out);
}